// round 13
// baseline (speedup 1.0000x reference)
#include <cuda_runtime.h>
#include <cuda_bf16.h>
#include <cstdint>

// BitLevelMapper: B=4194304 rows x 16 bits.
// bits:   [B,16] int32 {0,1}  (d_in[0])
// tables: [16, 32768] float32 {0,1} (d_in[1])
// out:    [B,16] float32
//
// R13: oct-per-thread layout (2 lanes per row, 32B per thread per iter).
// One shfl_xor completes the 16-bit pattern (was two), loop iterations
// halve (54 -> 27). Memory pattern identical (fully coalesced). PDL
// two-kernel structure, pre-sync load hoist, ballot pack from R12 kept.

#define NBITS   16
#define TSIZE   32768           // 2^15 entries per table row
#define NWORDS  2052            // sum over i of ceil(max(2^i,32)/32)

__device__ uint32_t g_packed[NWORDS];

// word offset of table row i in the packed layout
__host__ __device__ __forceinline__ int tab_off(int i) {
    return (i < 5) ? i : ((1 << (i - 5)) + 4);
}

// One warp per packed word: lane b reads entry lw*32+b, ballot packs.
__global__ void pack_tables_kernel(const float* __restrict__ tables) {
    int gw   = (blockIdx.x * blockDim.x + threadIdx.x) >> 5;
    int lane = threadIdx.x & 31;
    if (gw < NWORDS) {
        int i = 0;
        #pragma unroll
        for (int r = 1; r < 16; r++)
            if (gw >= tab_off(r)) i = r;
        int lw = gw - tab_off(i);
        float v = tables[(size_t)i * TSIZE + lw * 32 + lane];
        unsigned word = __ballot_sync(0xffffffffu, v != 0.0f);
        if (lane == 0) g_packed[gw] = word;
    }
    __threadfence();                              // order g_packed before signal
    cudaTriggerProgrammaticLaunchCompletion();    // release dependent launch early
}

#define MAP_BLOCKS  1216        // 152 SMs x 8 CTAs: one full resident wave
#define MAP_THREADS 256

// Process one oct (8 int32 = half a row). p = oct parity (0: bits j=0..7,
// 1: bits j=8..15). shift = 15 - 8p. Writes 8 floats.
__device__ __forceinline__ void oct_out(
    int4 a, int4 b, int shift, const uint32_t* __restrict__ s_tab,
    float4* __restrict__ dst)
{
    // partial pattern: value m (j = 8p+m) sits at bit position shift-m
    unsigned P = ((unsigned)a.x << shift)       | ((unsigned)a.y << (shift - 1))
               | ((unsigned)a.z << (shift - 2)) | ((unsigned)a.w << (shift - 3))
               | ((unsigned)b.x << (shift - 4)) | ((unsigned)b.y << (shift - 5))
               | ((unsigned)b.z << (shift - 6)) | ((unsigned)b.w << (shift - 7));
    // single OR-exchange with the partner lane completes the 16-bit pattern
    P |= __shfl_xor_sync(0xffffffffu, P, 1);

    float o[8];
    #pragma unroll
    for (int m = 0; m < 8; m++) {
        int i = shift - m;                             // table row index
        unsigned addr = P & ((1u << i) - 1u);          // prefix of context
        uint32_t wv = s_tab[tab_off(i) + (addr >> 5)];
        unsigned x = ((wv >> (addr & 31u)) ^ (P >> i)) & 1u;   // bit ^ flip
        o[m] = __uint_as_float((0u - x) & 0x3f800000u);        // x ? 1.0f : 0.0f
    }
    dst[0] = make_float4(o[0], o[1], o[2], o[3]);
    dst[1] = make_float4(o[4], o[5], o[6], o[7]);
}

__global__ void __launch_bounds__(MAP_THREADS, 8)
map_kernel(const int4* __restrict__ bits4, float4* __restrict__ out4, int nocts) {
    const int stride = gridDim.x * blockDim.x;
    const int base_t = blockIdx.x * blockDim.x + threadIdx.x;
    const int p      = base_t & 1;            // oct parity within the row
    const int shift  = 15 - 8 * p;            // bit position of a.x in pattern P
    const int nmain  = nocts / stride;        // uniform across all threads

    // First input load is independent of the pack — issue it before the
    // dependency sync so the wait overlaps the DRAM fetch.
    int4 a0 = bits4[(size_t)base_t * 2];
    int4 b0 = bits4[(size_t)base_t * 2 + 1];

    cudaGridDependencySynchronize();          // g_packed now valid

    __shared__ uint32_t s_tab[NWORDS];
    for (int t = threadIdx.x; t < NWORDS; t += blockDim.x)
        s_tab[t] = g_packed[t];
    __syncthreads();

    // iteration 0 (peeled, uses the pre-sync load)
    oct_out(a0, b0, shift, s_tab, out4 + (size_t)base_t * 2);

    // iterations 1..nmain; residual predicate is warp-uniform
    // ((nocts % stride) % 32 == 0) so the shuffle path is safe in the tail.
    for (int it = 1; it <= nmain; it++) {
        int t = base_t + it * stride;
        if (t >= nocts) break;                // warp-uniform exit
        int4 a = bits4[(size_t)t * 2];
        int4 b = bits4[(size_t)t * 2 + 1];
        oct_out(a, b, shift, s_tab, out4 + (size_t)t * 2);
    }
}

extern "C" void kernel_launch(void* const* d_in, const int* in_sizes, int n_in,
                              void* d_out, int out_size) {
    const int4*  bits4  = (const int4*)d_in[0];
    const float* tables = (const float*)d_in[1];
    float4*      out4   = (float4*)d_out;

    int nocts = in_sizes[0] / 8;       // 8388608

    pack_tables_kernel<<<(NWORDS * 32 + 255) / 256, 256>>>(tables);

    cudaLaunchConfig_t cfg = {};
    cfg.gridDim  = dim3(MAP_BLOCKS, 1, 1);
    cfg.blockDim = dim3(MAP_THREADS, 1, 1);
    cfg.dynamicSmemBytes = 0;
    cfg.stream = 0;                    // legacy default stream (capture target)
    cudaLaunchAttribute attr[1];
    attr[0].id = cudaLaunchAttributeProgrammaticStreamSerialization;
    attr[0].val.programmaticStreamSerializationAllowed = 1;
    cfg.attrs = attr;
    cfg.numAttrs = 1;
    cudaLaunchKernelEx(&cfg, map_kernel, bits4, out4, nocts);
}

// round 14
// speedup vs baseline: 1.1313x; 1.1313x over previous
#include <cuda_runtime.h>
#include <cuda_bf16.h>
#include <cstdint>

// BitLevelMapper: B=4194304 rows x 16 bits.
// bits:   [B,16] int32 {0,1}  (d_in[0])
// tables: [16, 32768] float32 {0,1} (d_in[1])
// out:    [B,16] float32
//
// R14 = R12 (best verified, 88.58us). Final composition:
//  - quad-per-thread layout: 4 lanes/row, every LDG/STG.128 fully
//    sector-packed (R2); oct layout falsified in R13 (stride-2 sectors).
//  - packed-bit table in smem, 4 LDS/iter (R5 body; fused LUT neutral).
//  - grid = 1216 = 152 SMs x 8 CTAs, one full resident wave (R5).
//  - warp-uniform quad tail, no scalar re-read amplification (R8/R9).
//  - PDL: pack signals early, map overlaps launch + first DRAM fetch
//    before cudaGridDependencySynchronize (R10/R12).
// Map runs at ~6.3TB/s effective = ~95% of the B300 mixed-stream LTS cap;
// total-map = ~7us measured harness floor. This is the roofline.

#define NBITS   16
#define TSIZE   32768           // 2^15 entries per table row
#define NWORDS  2052            // sum over i of ceil(max(2^i,32)/32)

__device__ uint32_t g_packed[NWORDS];

// word offset of table row i in the packed layout
__host__ __device__ __forceinline__ int tab_off(int i) {
    return (i < 5) ? i : ((1 << (i - 5)) + 4);
}

// One warp per packed word: lane b reads entry lw*32+b, ballot packs.
__global__ void pack_tables_kernel(const float* __restrict__ tables) {
    int gw   = (blockIdx.x * blockDim.x + threadIdx.x) >> 5;
    int lane = threadIdx.x & 31;
    if (gw < NWORDS) {
        int i = 0;
        #pragma unroll
        for (int r = 1; r < 16; r++)
            if (gw >= tab_off(r)) i = r;
        int lw = gw - tab_off(i);
        float v = tables[(size_t)i * TSIZE + lw * 32 + lane];
        unsigned word = __ballot_sync(0xffffffffu, v != 0.0f);
        if (lane == 0) g_packed[gw] = word;
    }
    __threadfence();                              // order g_packed before signal
    cudaTriggerProgrammaticLaunchCompletion();    // release dependent launch early
}

#define MAP_BLOCKS  1216        // 152 SMs x 8 CTAs: one full resident wave
#define MAP_THREADS 256

__device__ __forceinline__ float4 quad_out(
    int4 v, int shift, const uint32_t* __restrict__ s_tab)
{
    // partial 16-bit pattern: bit j (array order) sits at position 15-j
    unsigned P = ((unsigned)v.x << shift)       | ((unsigned)v.y << (shift - 1))
               | ((unsigned)v.z << (shift - 2)) | ((unsigned)v.w << (shift - 3));
    // OR-reduce across the aligned 4-lane group -> full pattern in all 4 lanes
    P |= __shfl_xor_sync(0xffffffffu, P, 1);
    P |= __shfl_xor_sync(0xffffffffu, P, 2);

    float o[4];
    #pragma unroll
    for (int m = 0; m < 4; m++) {
        int i = shift - m;                             // table row index
        unsigned addr = P & ((1u << i) - 1u);          // prefix of context
        uint32_t wv = s_tab[tab_off(i) + (addr >> 5)];
        unsigned x = ((wv >> (addr & 31u)) ^ (P >> i)) & 1u;   // bit ^ flip
        o[m] = __uint_as_float((0u - x) & 0x3f800000u);        // x ? 1.0f : 0.0f
    }
    return make_float4(o[0], o[1], o[2], o[3]);
}

__global__ void __launch_bounds__(MAP_THREADS, 8)
map_kernel(const int4* __restrict__ bits4, float4* __restrict__ out4, int nquads) {
    const int stride = gridDim.x * blockDim.x;
    const int base_t = blockIdx.x * blockDim.x + threadIdx.x;
    const int q      = base_t & 3;           // quarter within row (lane-group pos)
    const int shift  = 15 - 4 * q;           // bit position of v.x in pattern P
    const int nmain  = nquads / stride;      // uniform across all threads

    // First input load is independent of the pack — issue it before the
    // dependency sync so the wait overlaps the DRAM fetch.
    int4 v0 = bits4[base_t];                 // base_t < nquads always here

    cudaGridDependencySynchronize();         // g_packed now valid

    __shared__ uint32_t s_tab[NWORDS];
    for (int t = threadIdx.x; t < NWORDS; t += blockDim.x)
        s_tab[t] = g_packed[t];
    __syncthreads();

    // iteration 0 (peeled, uses the pre-sync load)
    out4[base_t] = quad_out(v0, shift, s_tab);

    // iterations 1..nmain; residual predicate is warp-uniform
    // ((nquads % stride) % 32 == 0) so the shuffle path is safe in the tail.
    for (int it = 1; it <= nmain; it++) {
        int t = base_t + it * stride;
        if (t >= nquads) break;              // warp-uniform exit
        int4 v = bits4[t];
        out4[t] = quad_out(v, shift, s_tab);
    }
}

extern "C" void kernel_launch(void* const* d_in, const int* in_sizes, int n_in,
                              void* d_out, int out_size) {
    const int4*  bits4  = (const int4*)d_in[0];
    const float* tables = (const float*)d_in[1];
    float4*      out4   = (float4*)d_out;

    int nquads = in_sizes[0] / 4;      // 16777216

    pack_tables_kernel<<<(NWORDS * 32 + 255) / 256, 256>>>(tables);

    cudaLaunchConfig_t cfg = {};
    cfg.gridDim  = dim3(MAP_BLOCKS, 1, 1);
    cfg.blockDim = dim3(MAP_THREADS, 1, 1);
    cfg.dynamicSmemBytes = 0;
    cfg.stream = 0;                    // legacy default stream (capture target)
    cudaLaunchAttribute attr[1];
    attr[0].id = cudaLaunchAttributeProgrammaticStreamSerialization;
    attr[0].val.programmaticStreamSerializationAllowed = 1;
    cfg.attrs = attr;
    cfg.numAttrs = 1;
    cudaLaunchKernelEx(&cfg, map_kernel, bits4, out4, nquads);
}